// round 5
// baseline (speedup 1.0000x reference)
#include <cuda_runtime.h>
#include <cuda_fp16.h>
#include <cstdint>
#include <math.h>

// ---------------------------------------------------------------------------
// lstm_30734785970219: z = [x|h] @ W (M=4096, K=2048, N=4096) + fused gates.
// R5: bf16 -> fp16 operands (11-bit mantissa) to fix rel_err 1.36e-3 -> ~2e-4.
// ldmatrix + mma.sync.m16n8k16.f16, fp32 accum. N reordered n' = 4*j + gate
// so a 128-col tile holds all 4 gates for 32 hidden units; fused LSTM epilogue.
// ---------------------------------------------------------------------------

static constexpr int MDIM = 4096;   // B*T
static constexpr int NDIM = 4096;   // 4*H (gate-interleaved)
static constexpr int KDIM = 2048;   // D_IN + H
static constexpr int HDIM = 1024;

static constexpr int BM = 128, BN = 128, BK = 64;
static constexpr int STAGES = 4;
static constexpr int NCHUNK = KDIM / BK;                  // 32
static constexpr int STAGE_BYTES = (BM + BN) * BK * 2;    // 32 KB
static constexpr int SMEM_BIAS = STAGES * STAGE_BYTES;    // 131072
static constexpr int SMEM_TOTAL = SMEM_BIAS + 512;        // 131584
static constexpr int ZSTRIDE = 132;                       // f32 row stride (pad)

// Scratch (allocation-free rule: __device__ globals)
__device__ __half g_A[(size_t)MDIM * KDIM];
__device__ __half g_Wt[(size_t)NDIM * KDIM];
__device__ __align__(16) float g_bias[NDIM];

// ---------------------------------------------------------------------------
// helpers
// ---------------------------------------------------------------------------
__device__ __forceinline__ uint32_t smem_to_u32(const void* p) {
    uint32_t a;
    asm("{ .reg .u64 t; cvta.to.shared.u64 t, %1; cvt.u32.u64 %0, t; }"
        : "=r"(a) : "l"(p));
    return a;
}

__device__ __forceinline__ void cp_async_16(uint32_t smem, const void* gmem) {
    asm volatile("cp.async.cg.shared.global [%0], [%1], 16;"
                 :: "r"(smem), "l"(gmem));
}
#define CP_COMMIT() asm volatile("cp.async.commit_group;" ::: "memory")
#define CP_WAIT(n)  asm volatile("cp.async.wait_group %0;" :: "n"(n) : "memory")

__device__ __forceinline__ void ldmatrix_x4(uint32_t& r0, uint32_t& r1,
                                            uint32_t& r2, uint32_t& r3,
                                            uint32_t addr) {
    asm volatile("ldmatrix.sync.aligned.m8n8.x4.shared.b16 {%0,%1,%2,%3}, [%4];"
                 : "=r"(r0), "=r"(r1), "=r"(r2), "=r"(r3) : "r"(addr));
}

__device__ __forceinline__ void mma_fp16(float* d, const uint32_t* a,
                                         uint32_t b0, uint32_t b1) {
    asm volatile(
        "mma.sync.aligned.m16n8k16.row.col.f32.f16.f16.f32 "
        "{%0,%1,%2,%3}, {%4,%5,%6,%7}, {%8,%9}, {%0,%1,%2,%3};"
        : "+f"(d[0]), "+f"(d[1]), "+f"(d[2]), "+f"(d[3])
        : "r"(a[0]), "r"(a[1]), "r"(a[2]), "r"(a[3]), "r"(b0), "r"(b1));
}

// ---------------------------------------------------------------------------
// Pre-pass kernels
// ---------------------------------------------------------------------------
__global__ void pack_a_kernel(const float* __restrict__ x,
                              const float* __restrict__ h) {
    int idx = blockIdx.x * blockDim.x + threadIdx.x;    // 2,097,152 float4s
    int m = idx >> 9;
    int k = (idx & 511) << 2;
    const float* src = (k < HDIM) ? (x + (size_t)m * HDIM + k)
                                  : (h + (size_t)m * HDIM + (k - HDIM));
    float4 v = *reinterpret_cast<const float4*>(src);
    __half2* dst = reinterpret_cast<__half2*>(g_A + (size_t)m * KDIM + k);
    dst[0] = __floats2half2_rn(v.x, v.y);
    dst[1] = __floats2half2_rn(v.z, v.w);
}

// Wt[4*j+gate][k] = W_gate[k][j]  (fp16). 32x32 tiled transpose.
__global__ void transpose_w_kernel(const float* __restrict__ Wf,
                                   const float* __restrict__ Wi,
                                   const float* __restrict__ Wg,
                                   const float* __restrict__ Wo) {
    __shared__ float s[32][33];
    int gate = blockIdx.z;
    const float* W = (gate == 0) ? Wf : (gate == 1) ? Wi : (gate == 2) ? Wg : Wo;
    int j0 = blockIdx.x * 32;
    int k0 = blockIdx.y * 32;
    int tx = threadIdx.x, ty = threadIdx.y;
    #pragma unroll
    for (int kk = ty; kk < 32; kk += 8)
        s[kk][tx] = W[(size_t)(k0 + kk) * HDIM + j0 + tx];
    __syncthreads();
    #pragma unroll
    for (int jj = ty; jj < 32; jj += 8) {
        size_t r = (size_t)((j0 + jj) * 4 + gate);
        g_Wt[r * KDIM + k0 + tx] = __float2half_rn(s[tx][jj]);
    }
}

__global__ void pack_bias_kernel(const float* __restrict__ bf,
                                 const float* __restrict__ bi,
                                 const float* __restrict__ bg,
                                 const float* __restrict__ bo) {
    int j = blockIdx.x * blockDim.x + threadIdx.x;
    if (j < HDIM) {
        reinterpret_cast<float4*>(g_bias)[j] =
            make_float4(bf[j], bi[j], bg[j], bo[j]);
    }
}

// ---------------------------------------------------------------------------
// Main GEMM + fused LSTM epilogue (256 threads, 8 warps: 4(m) x 2(n))
// ---------------------------------------------------------------------------
__global__ __launch_bounds__(256)
void lstm_gemm_kernel(const float* __restrict__ c_in, float* __restrict__ out) {
    extern __shared__ char smem[];
    const uint32_t smem_u32 = smem_to_u32(smem);
    const int tid = threadIdx.x;
    const int wid = tid >> 5;
    const int lane = tid & 31;
    const int warp_m = wid & 3;       // 0..3 -> 32 rows each
    const int warp_n = wid >> 2;      // 0..1 -> 64 cols each
    const int m0 = blockIdx.y * BM;
    const int r0 = blockIdx.x * BN;   // gate-interleaved column base
    const int jb = blockIdx.x * 32;   // hidden-unit base

    float* bias_s = reinterpret_cast<float*>(smem + SMEM_BIAS);
    if (tid < 128) bias_s[tid] = g_bias[r0 + tid];

    // --- cp.async producers: each thread does 4 A + 4 B 16B copies/stage ---
    const int ci = tid & 7;           // 16B chunk in a 128B row
    const int crb = tid >> 3;         // row base (0..31)
    const __half* gA = g_A  + (size_t)m0 * KDIM + ci * 8;
    const __half* gB = g_Wt + (size_t)r0 * KDIM + ci * 8;

    auto load_stage = [&](int stage, int kc) {
        const uint32_t sm = smem_u32 + stage * STAGE_BYTES;
        #pragma unroll
        for (int rep = 0; rep < 4; ++rep) {
            const int row = crb + rep * 32;
            const uint32_t sw = row * 128 + ((ci ^ (row & 7)) << 4);
            cp_async_16(sm + sw, gA + (size_t)row * KDIM + kc);
            cp_async_16(sm + BM * 128 + sw, gB + (size_t)row * KDIM + kc);
        }
    };

    // prologue: stages 0..2
    #pragma unroll
    for (int s = 0; s < STAGES - 1; ++s) {
        load_stage(s, s * BK);
        CP_COMMIT();
    }

    float acc[2][8][4];
    #pragma unroll
    for (int mt = 0; mt < 2; ++mt)
        #pragma unroll
        for (int nt = 0; nt < 8; ++nt)
            #pragma unroll
            for (int e = 0; e < 4; ++e) acc[mt][nt][e] = 0.0f;

    const int lrow = lane & 15;
    const int lhalf = lane >> 4;

    #pragma unroll 1
    for (int c = 0; c < NCHUNK; ++c) {
        __syncthreads();               // compute on stage (c-1)&3 done everywhere
        if (c + STAGES - 1 < NCHUNK)
            load_stage((c + STAGES - 1) & 3, (c + STAGES - 1) * BK);
        CP_COMMIT();
        CP_WAIT(STAGES - 1);           // chunk c resident
        __syncthreads();

        const uint32_t smA = smem_u32 + (c & 3) * STAGE_BYTES;
        const uint32_t smB = smA + BM * 128;

        #pragma unroll
        for (int ks = 0; ks < 4; ++ks) {
            const int chunk = ks * 2 + lhalf;
            uint32_t a[2][4];
            #pragma unroll
            for (int mt = 0; mt < 2; ++mt) {
                const int row = warp_m * 32 + mt * 16 + lrow;
                ldmatrix_x4(a[mt][0], a[mt][1], a[mt][2], a[mt][3],
                            smA + row * 128 + ((chunk ^ (row & 7)) << 4));
            }
            uint32_t b[4][4];
            #pragma unroll
            for (int nt2 = 0; nt2 < 4; ++nt2) {
                const int row = warp_n * 64 + nt2 * 16 + lrow;
                ldmatrix_x4(b[nt2][0], b[nt2][1], b[nt2][2], b[nt2][3],
                            smB + row * 128 + ((chunk ^ (row & 7)) << 4));
            }
            #pragma unroll
            for (int mt = 0; mt < 2; ++mt)
                #pragma unroll
                for (int nt = 0; nt < 8; ++nt)
                    mma_fp16(acc[mt][nt], a[mt],
                             b[nt >> 1][nt & 1], b[nt >> 1][(nt & 1) + 2]);
        }
    }

    // ---------------- epilogue: stage z through smem, fuse LSTM ----------------
    __syncthreads();
    float* zbuf = reinterpret_cast<float*>(smem);
    {
        const int rb = warp_m * 32 + (lane >> 2);
        const int cb = warp_n * 64 + (lane & 3) * 2;
        #pragma unroll
        for (int mt = 0; mt < 2; ++mt)
            #pragma unroll
            for (int nt = 0; nt < 8; ++nt) {
                const int r = rb + mt * 16;
                const int cc = cb + nt * 8;
                zbuf[r * ZSTRIDE + cc]           = acc[mt][nt][0];
                zbuf[r * ZSTRIDE + cc + 1]       = acc[mt][nt][1];
                zbuf[(r + 8) * ZSTRIDE + cc]     = acc[mt][nt][2];
                zbuf[(r + 8) * ZSTRIDE + cc + 1] = acc[mt][nt][3];
            }
    }
    __syncthreads();

    {
        const int r = tid >> 1;                 // 0..127 local row
        const int jh = (tid & 1) * 16;          // 16 hidden units per thread
        const size_t m = (size_t)(m0 + r);
        const float* cin = c_in + m * HDIM + jb;
        float* hout = out + m * HDIM + jb;
        float* cout = out + (size_t)MDIM * HDIM + m * HDIM + jb;
        const float* zrow = zbuf + r * ZSTRIDE;

        #pragma unroll
        for (int q = 0; q < 4; ++q) {
            const int j0 = jh + q * 4;
            float4 ci4 = *reinterpret_cast<const float4*>(cin + j0);
            const float* cip = &ci4.x;
            float hv[4], cv[4];
            #pragma unroll
            for (int e = 0; e < 4; ++e) {
                const int j = j0 + e;
                float4 z4 = *reinterpret_cast<const float4*>(zrow + j * 4);
                float4 b4 = *reinterpret_cast<const float4*>(bias_s + j * 4);
                float zf = z4.x + b4.x, zi = z4.y + b4.y;
                float zg = z4.z + b4.z, zo = z4.w + b4.w;
                float f = 1.0f / (1.0f + __expf(-zf));
                float i = 1.0f / (1.0f + __expf(-zi));
                float g = tanhf(zg);
                float o = 1.0f / (1.0f + __expf(-zo));
                float cval = f * cip[e] + g * i;
                cv[e] = cval;
                hv[e] = tanhf(cval) * o;
            }
            *reinterpret_cast<float4*>(hout + j0) =
                make_float4(hv[0], hv[1], hv[2], hv[3]);
            *reinterpret_cast<float4*>(cout + j0) =
                make_float4(cv[0], cv[1], cv[2], cv[3]);
        }
    }
}

// ---------------------------------------------------------------------------
// kernel_launch
// ---------------------------------------------------------------------------
extern "C" void kernel_launch(void* const* d_in, const int* in_sizes, int n_in,
                              void* d_out, int out_size) {
    const float* x    = (const float*)d_in[0];
    const float* h_in = (const float*)d_in[1];
    const float* c_in = (const float*)d_in[2];
    const float* Wf   = (const float*)d_in[3];
    const float* bf   = (const float*)d_in[4];
    const float* Wi   = (const float*)d_in[5];
    const float* bi   = (const float*)d_in[6];
    const float* Wg   = (const float*)d_in[7];
    const float* bg   = (const float*)d_in[8];
    const float* Wo   = (const float*)d_in[9];
    const float* bo   = (const float*)d_in[10];
    float* out = (float*)d_out;

    pack_a_kernel<<<(MDIM * KDIM / 4) / 256, 256>>>(x, h_in);
    transpose_w_kernel<<<dim3(HDIM / 32, KDIM / 32, 4), dim3(32, 8)>>>(Wf, Wi, Wg, Wo);
    pack_bias_kernel<<<4, 256>>>(bf, bi, bg, bo);

    cudaFuncSetAttribute(lstm_gemm_kernel,
                         cudaFuncAttributeMaxDynamicSharedMemorySize, SMEM_TOTAL);
    lstm_gemm_kernel<<<dim3(NDIM / BN, MDIM / BM), 256, SMEM_TOTAL>>>(c_in, out);
}

// round 7
// speedup vs baseline: 1.1897x; 1.1897x over previous
#include <cuda_runtime.h>
#include <cuda_fp16.h>
#include <cstdint>
#include <math.h>

// ---------------------------------------------------------------------------
// lstm_30734785970219: z = [x|h] @ W (M=4096, K=2048, N=4096) + fused gates.
// R6 resubmit (R6 bench = container-acquisition infra failure, no signal).
// Occupancy fix: STAGES 4->3 (98.8KB smem) + launch_bounds(256,2) gives
// 2 CTAs/SM (occ 25%); single-barrier pipeline; hoisted addressing.
// fp16 operands, fp32 accum (R5: rel_err 1.7e-4). Gate-interleaved N.
// ---------------------------------------------------------------------------

static constexpr int MDIM = 4096;   // B*T
static constexpr int NDIM = 4096;   // 4*H (gate-interleaved)
static constexpr int KDIM = 2048;   // D_IN + H
static constexpr int HDIM = 1024;

static constexpr int BM = 128, BN = 128, BK = 64;
static constexpr int STAGES = 3;
static constexpr int NCHUNK = KDIM / BK;                  // 32
static constexpr int STAGE_BYTES = (BM + BN) * BK * 2;    // 32 KB
static constexpr int SMEM_BIAS = STAGES * STAGE_BYTES;    // 98304
static constexpr int SMEM_TOTAL = SMEM_BIAS + 512;        // 98816 -> 2 CTAs/SM
static constexpr int ZSTRIDE = 132;                       // f32 row stride (pad)

// Scratch (allocation-free rule: __device__ globals)
__device__ __half g_A[(size_t)MDIM * KDIM];
__device__ __half g_Wt[(size_t)NDIM * KDIM];
__device__ __align__(16) float g_bias[NDIM];

// ---------------------------------------------------------------------------
// helpers
// ---------------------------------------------------------------------------
__device__ __forceinline__ uint32_t smem_to_u32(const void* p) {
    uint32_t a;
    asm("{ .reg .u64 t; cvta.to.shared.u64 t, %1; cvt.u32.u64 %0, t; }"
        : "=r"(a) : "l"(p));
    return a;
}

__device__ __forceinline__ void cp_async_16(uint32_t smem, const void* gmem) {
    asm volatile("cp.async.cg.shared.global [%0], [%1], 16;"
                 :: "r"(smem), "l"(gmem));
}
#define CP_COMMIT() asm volatile("cp.async.commit_group;" ::: "memory")
#define CP_WAIT(n)  asm volatile("cp.async.wait_group %0;" :: "n"(n) : "memory")

__device__ __forceinline__ void ldmatrix_x4(uint32_t& r0, uint32_t& r1,
                                            uint32_t& r2, uint32_t& r3,
                                            uint32_t addr) {
    asm volatile("ldmatrix.sync.aligned.m8n8.x4.shared.b16 {%0,%1,%2,%3}, [%4];"
                 : "=r"(r0), "=r"(r1), "=r"(r2), "=r"(r3) : "r"(addr));
}

__device__ __forceinline__ void mma_fp16(float* d, const uint32_t* a,
                                         uint32_t b0, uint32_t b1) {
    asm volatile(
        "mma.sync.aligned.m16n8k16.row.col.f32.f16.f16.f32 "
        "{%0,%1,%2,%3}, {%4,%5,%6,%7}, {%8,%9}, {%0,%1,%2,%3};"
        : "+f"(d[0]), "+f"(d[1]), "+f"(d[2]), "+f"(d[3])
        : "r"(a[0]), "r"(a[1]), "r"(a[2]), "r"(a[3]), "r"(b0), "r"(b1));
}

// ---------------------------------------------------------------------------
// Pre-pass kernels
// ---------------------------------------------------------------------------
__global__ void pack_a_kernel(const float* __restrict__ x,
                              const float* __restrict__ h) {
    int idx = blockIdx.x * blockDim.x + threadIdx.x;    // 2,097,152 float4s
    int m = idx >> 9;
    int k = (idx & 511) << 2;
    const float* src = (k < HDIM) ? (x + (size_t)m * HDIM + k)
                                  : (h + (size_t)m * HDIM + (k - HDIM));
    float4 v = *reinterpret_cast<const float4*>(src);
    __half2* dst = reinterpret_cast<__half2*>(g_A + (size_t)m * KDIM + k);
    dst[0] = __floats2half2_rn(v.x, v.y);
    dst[1] = __floats2half2_rn(v.z, v.w);
}

// Wt[4*j+gate][k] = W_gate[k][j]  (fp16). 32x32 tiled transpose.
__global__ void transpose_w_kernel(const float* __restrict__ Wf,
                                   const float* __restrict__ Wi,
                                   const float* __restrict__ Wg,
                                   const float* __restrict__ Wo) {
    __shared__ float s[32][33];
    int gate = blockIdx.z;
    const float* W = (gate == 0) ? Wf : (gate == 1) ? Wi : (gate == 2) ? Wg : Wo;
    int j0 = blockIdx.x * 32;
    int k0 = blockIdx.y * 32;
    int tx = threadIdx.x, ty = threadIdx.y;
    #pragma unroll
    for (int kk = ty; kk < 32; kk += 8)
        s[kk][tx] = W[(size_t)(k0 + kk) * HDIM + j0 + tx];
    __syncthreads();
    #pragma unroll
    for (int jj = ty; jj < 32; jj += 8) {
        size_t r = (size_t)((j0 + jj) * 4 + gate);
        g_Wt[r * KDIM + k0 + tx] = __float2half_rn(s[tx][jj]);
    }
}

__global__ void pack_bias_kernel(const float* __restrict__ bf,
                                 const float* __restrict__ bi,
                                 const float* __restrict__ bg,
                                 const float* __restrict__ bo) {
    int j = blockIdx.x * blockDim.x + threadIdx.x;
    if (j < HDIM) {
        reinterpret_cast<float4*>(g_bias)[j] =
            make_float4(bf[j], bi[j], bg[j], bo[j]);
    }
}

// ---------------------------------------------------------------------------
// Main GEMM + fused LSTM epilogue (256 threads, 8 warps: 4(m) x 2(n))
// ---------------------------------------------------------------------------
__global__ __launch_bounds__(256, 2)
void lstm_gemm_kernel(const float* __restrict__ c_in, float* __restrict__ out) {
    extern __shared__ char smem[];
    const uint32_t smem_u32 = smem_to_u32(smem);
    const int tid = threadIdx.x;
    const int wid = tid >> 5;
    const int lane = tid & 31;
    const int warp_m = wid & 3;       // 0..3 -> 32 rows each
    const int warp_n = wid >> 2;      // 0..1 -> 64 cols each
    const int m0 = blockIdx.y * BM;
    const int r0 = blockIdx.x * BN;   // gate-interleaved column base
    const int jb = blockIdx.x * 32;   // hidden-unit base

    float* bias_s = reinterpret_cast<float*>(smem + SMEM_BIAS);
    if (tid < 128) bias_s[tid] = g_bias[r0 + tid];

    // --- cp.async producers: hoisted pointers/offsets (4 A + 4 B per stage) ---
    const int ci = tid & 7;           // 16B chunk in a 128B row
    const int crb = tid >> 3;         // row base (0..31)
    const __half* pA[4];
    const __half* pB[4];
    uint32_t swoff[4];
    #pragma unroll
    for (int rep = 0; rep < 4; ++rep) {
        const int row = crb + rep * 32;
        swoff[rep] = (uint32_t)(row * 128 + ((ci ^ (row & 7)) << 4));
        pA[rep] = g_A  + (size_t)(m0 + row) * KDIM + ci * 8;
        pB[rep] = g_Wt + (size_t)(r0 + row) * KDIM + ci * 8;
    }

    auto load_stage = [&](int stage, int kc) {
        const uint32_t sm = smem_u32 + stage * STAGE_BYTES;
        #pragma unroll
        for (int rep = 0; rep < 4; ++rep) {
            cp_async_16(sm + swoff[rep], pA[rep] + kc);
            cp_async_16(sm + BM * 128 + swoff[rep], pB[rep] + kc);
        }
    };

    // prologue: stages 0,1 (group #0, #1)
    load_stage(0, 0);
    CP_COMMIT();
    load_stage(1, BK);
    CP_COMMIT();

    float acc[2][8][4];
    #pragma unroll
    for (int mt = 0; mt < 2; ++mt)
        #pragma unroll
        for (int nt = 0; nt < 8; ++nt)
            #pragma unroll
            for (int e = 0; e < 4; ++e) acc[mt][nt][e] = 0.0f;

    const int lrow = lane & 15;
    const int lhalf = lane >> 4;

    // Hoisted ldmatrix row offsets. Stage bases are 32KB-aligned and row*128
    // has bits[4:6] clear, so the swizzle XOR can apply to the full address.
    uint32_t rowA[2], rowB[4];
    #pragma unroll
    for (int mt = 0; mt < 2; ++mt) {
        const int row = warp_m * 32 + mt * 16 + lrow;
        rowA[mt] = (uint32_t)(row * 128 + ((row & 7) << 4));
    }
    #pragma unroll
    for (int nt2 = 0; nt2 < 4; ++nt2) {
        const int row = warp_n * 64 + nt2 * 16 + lrow;
        rowB[nt2] = (uint32_t)(row * 128 + ((row & 7) << 4));
    }

    // Single-barrier pipeline: group #g carries stage g; always commit so the
    // wait_group(1) at iter c guarantees group #c (stage c%3) is resident.
    #pragma unroll 1
    for (int c = 0; c < NCHUNK; ++c) {
        CP_WAIT(1);                    // stage c resident (this thread's part)
        __syncthreads();               // all threads' parts visible; stage c-1 free
        if (c + 2 < NCHUNK)
            load_stage((c + 2) % 3, (c + 2) * BK);
        CP_COMMIT();                   // empty group near the tail — still counts

        const uint32_t smA = smem_u32 + (c % 3) * STAGE_BYTES;
        const uint32_t smB = smA + BM * 128;

        #pragma unroll
        for (int ks = 0; ks < 4; ++ks) {
            const uint32_t cx = (uint32_t)((ks * 2 + lhalf) << 4);
            uint32_t a[2][4];
            #pragma unroll
            for (int mt = 0; mt < 2; ++mt)
                ldmatrix_x4(a[mt][0], a[mt][1], a[mt][2], a[mt][3],
                            (smA + rowA[mt]) ^ cx);
            uint32_t b[4][4];
            #pragma unroll
            for (int nt2 = 0; nt2 < 4; ++nt2)
                ldmatrix_x4(b[nt2][0], b[nt2][1], b[nt2][2], b[nt2][3],
                            (smB + rowB[nt2]) ^ cx);
            #pragma unroll
            for (int mt = 0; mt < 2; ++mt)
                #pragma unroll
                for (int nt = 0; nt < 8; ++nt)
                    mma_fp16(acc[mt][nt], a[mt],
                             b[nt >> 1][nt & 1], b[nt >> 1][(nt & 1) + 2]);
        }
    }

    // ---------------- epilogue: stage z through smem, fuse LSTM ----------------
    CP_WAIT(0);
    __syncthreads();
    float* zbuf = reinterpret_cast<float*>(smem);
    {
        const int rb = warp_m * 32 + (lane >> 2);
        const int cb = warp_n * 64 + (lane & 3) * 2;
        #pragma unroll
        for (int mt = 0; mt < 2; ++mt)
            #pragma unroll
            for (int nt = 0; nt < 8; ++nt) {
                const int r = rb + mt * 16;
                const int cc = cb + nt * 8;
                zbuf[r * ZSTRIDE + cc]           = acc[mt][nt][0];
                zbuf[r * ZSTRIDE + cc + 1]       = acc[mt][nt][1];
                zbuf[(r + 8) * ZSTRIDE + cc]     = acc[mt][nt][2];
                zbuf[(r + 8) * ZSTRIDE + cc + 1] = acc[mt][nt][3];
            }
    }
    __syncthreads();

    {
        const int r = tid >> 1;                 // 0..127 local row
        const int jh = (tid & 1) * 16;          // 16 hidden units per thread
        const size_t m = (size_t)(m0 + r);
        const float* cin = c_in + m * HDIM + jb;
        float* hout = out + m * HDIM + jb;
        float* cout = out + (size_t)MDIM * HDIM + m * HDIM + jb;
        const float* zrow = zbuf + r * ZSTRIDE;

        #pragma unroll
        for (int q = 0; q < 4; ++q) {
            const int j0 = jh + q * 4;
            float4 ci4 = *reinterpret_cast<const float4*>(cin + j0);
            const float* cip = &ci4.x;
            float hv[4], cv[4];
            #pragma unroll
            for (int e = 0; e < 4; ++e) {
                const int j = j0 + e;
                float4 z4 = *reinterpret_cast<const float4*>(zrow + j * 4);
                float4 b4 = *reinterpret_cast<const float4*>(bias_s + j * 4);
                float zf = z4.x + b4.x, zi = z4.y + b4.y;
                float zg = z4.z + b4.z, zo = z4.w + b4.w;
                float f = 1.0f / (1.0f + __expf(-zf));
                float i = 1.0f / (1.0f + __expf(-zi));
                float g = tanhf(zg);
                float o = 1.0f / (1.0f + __expf(-zo));
                float cval = f * cip[e] + g * i;
                cv[e] = cval;
                hv[e] = tanhf(cval) * o;
            }
            *reinterpret_cast<float4*>(hout + j0) =
                make_float4(hv[0], hv[1], hv[2], hv[3]);
            *reinterpret_cast<float4*>(cout + j0) =
                make_float4(cv[0], cv[1], cv[2], cv[3]);
        }
    }
}

// ---------------------------------------------------------------------------
// kernel_launch
// ---------------------------------------------------------------------------
extern "C" void kernel_launch(void* const* d_in, const int* in_sizes, int n_in,
                              void* d_out, int out_size) {
    const float* x    = (const float*)d_in[0];
    const float* h_in = (const float*)d_in[1];
    const float* c_in = (const float*)d_in[2];
    const float* Wf   = (const float*)d_in[3];
    const float* bf   = (const float*)d_in[4];
    const float* Wi   = (const float*)d_in[5];
    const float* bi   = (const float*)d_in[6];
    const float* Wg   = (const float*)d_in[7];
    const float* bg   = (const float*)d_in[8];
    const float* Wo   = (const float*)d_in[9];
    const float* bo   = (const float*)d_in[10];
    float* out = (float*)d_out;

    pack_a_kernel<<<(MDIM * KDIM / 4) / 256, 256>>>(x, h_in);
    transpose_w_kernel<<<dim3(HDIM / 32, KDIM / 32, 4), dim3(32, 8)>>>(Wf, Wi, Wg, Wo);
    pack_bias_kernel<<<4, 256>>>(bf, bi, bg, bo);

    cudaFuncSetAttribute(lstm_gemm_kernel,
                         cudaFuncAttributeMaxDynamicSharedMemorySize, SMEM_TOTAL);
    lstm_gemm_kernel<<<dim3(NDIM / BN, MDIM / BM), 256, SMEM_TOTAL>>>(c_in, out);
}

// round 8
// speedup vs baseline: 1.2293x; 1.0334x over previous
#include <cuda_runtime.h>
#include <cuda_fp16.h>
#include <cstdint>
#include <math.h>

// ---------------------------------------------------------------------------
// lstm_30734785970219: z = [x|h] @ W (M=4096, K=2048, N=4096) + fused gates.
// R8: pipeline reorder (prefetch issued BEFORE stage wait) + strength-reduced
// stage/pointer addressing. 3-stage cp.async, 2 CTAs/SM, fp16 mma.sync.
// Gate-interleaved N (n' = 4*j + gate); fused LSTM epilogue.
// ---------------------------------------------------------------------------

static constexpr int MDIM = 4096;   // B*T
static constexpr int NDIM = 4096;   // 4*H (gate-interleaved)
static constexpr int KDIM = 2048;   // D_IN + H
static constexpr int HDIM = 1024;

static constexpr int BM = 128, BN = 128, BK = 64;
static constexpr int NCHUNK = KDIM / BK;                  // 32
static constexpr int STAGE_BYTES = (BM + BN) * BK * 2;    // 32 KB
static constexpr int SMEM_BIAS = 3 * STAGE_BYTES;         // 98304
static constexpr int SMEM_TOTAL = SMEM_BIAS + 512;        // 98816 -> 2 CTAs/SM
static constexpr int ZSTRIDE = 132;                       // f32 row stride (pad)

// Scratch (allocation-free rule: __device__ globals)
__device__ __half g_A[(size_t)MDIM * KDIM];
__device__ __half g_Wt[(size_t)NDIM * KDIM];
__device__ __align__(16) float g_bias[NDIM];

// ---------------------------------------------------------------------------
// helpers
// ---------------------------------------------------------------------------
__device__ __forceinline__ uint32_t smem_to_u32(const void* p) {
    uint32_t a;
    asm("{ .reg .u64 t; cvta.to.shared.u64 t, %1; cvt.u32.u64 %0, t; }"
        : "=r"(a) : "l"(p));
    return a;
}

__device__ __forceinline__ void cp_async_16(uint32_t smem, const void* gmem) {
    asm volatile("cp.async.cg.shared.global [%0], [%1], 16;"
                 :: "r"(smem), "l"(gmem));
}
#define CP_COMMIT() asm volatile("cp.async.commit_group;" ::: "memory")
#define CP_WAIT(n)  asm volatile("cp.async.wait_group %0;" :: "n"(n) : "memory")

__device__ __forceinline__ void ldmatrix_x4(uint32_t& r0, uint32_t& r1,
                                            uint32_t& r2, uint32_t& r3,
                                            uint32_t addr) {
    asm volatile("ldmatrix.sync.aligned.m8n8.x4.shared.b16 {%0,%1,%2,%3}, [%4];"
                 : "=r"(r0), "=r"(r1), "=r"(r2), "=r"(r3) : "r"(addr));
}

__device__ __forceinline__ void mma_fp16(float* d, const uint32_t* a,
                                         uint32_t b0, uint32_t b1) {
    asm volatile(
        "mma.sync.aligned.m16n8k16.row.col.f32.f16.f16.f32 "
        "{%0,%1,%2,%3}, {%4,%5,%6,%7}, {%8,%9}, {%0,%1,%2,%3};"
        : "+f"(d[0]), "+f"(d[1]), "+f"(d[2]), "+f"(d[3])
        : "r"(a[0]), "r"(a[1]), "r"(a[2]), "r"(a[3]), "r"(b0), "r"(b1));
}

// ---------------------------------------------------------------------------
// Pre-pass kernels
// ---------------------------------------------------------------------------
__global__ void pack_a_kernel(const float* __restrict__ x,
                              const float* __restrict__ h) {
    int idx = blockIdx.x * blockDim.x + threadIdx.x;    // 2,097,152 float4s
    int m = idx >> 9;
    int k = (idx & 511) << 2;
    const float* src = (k < HDIM) ? (x + (size_t)m * HDIM + k)
                                  : (h + (size_t)m * HDIM + (k - HDIM));
    float4 v = *reinterpret_cast<const float4*>(src);
    __half2* dst = reinterpret_cast<__half2*>(g_A + (size_t)m * KDIM + k);
    dst[0] = __floats2half2_rn(v.x, v.y);
    dst[1] = __floats2half2_rn(v.z, v.w);
}

// Wt[4*j+gate][k] = W_gate[k][j]  (fp16). 32x32 tiled transpose.
__global__ void transpose_w_kernel(const float* __restrict__ Wf,
                                   const float* __restrict__ Wi,
                                   const float* __restrict__ Wg,
                                   const float* __restrict__ Wo) {
    __shared__ float s[32][33];
    int gate = blockIdx.z;
    const float* W = (gate == 0) ? Wf : (gate == 1) ? Wi : (gate == 2) ? Wg : Wo;
    int j0 = blockIdx.x * 32;
    int k0 = blockIdx.y * 32;
    int tx = threadIdx.x, ty = threadIdx.y;
    #pragma unroll
    for (int kk = ty; kk < 32; kk += 8)
        s[kk][tx] = W[(size_t)(k0 + kk) * HDIM + j0 + tx];
    __syncthreads();
    #pragma unroll
    for (int jj = ty; jj < 32; jj += 8) {
        size_t r = (size_t)((j0 + jj) * 4 + gate);
        g_Wt[r * KDIM + k0 + tx] = __float2half_rn(s[tx][jj]);
    }
}

__global__ void pack_bias_kernel(const float* __restrict__ bf,
                                 const float* __restrict__ bi,
                                 const float* __restrict__ bg,
                                 const float* __restrict__ bo) {
    int j = blockIdx.x * blockDim.x + threadIdx.x;
    if (j < HDIM) {
        reinterpret_cast<float4*>(g_bias)[j] =
            make_float4(bf[j], bi[j], bg[j], bo[j]);
    }
}

// ---------------------------------------------------------------------------
// Main GEMM + fused LSTM epilogue (256 threads, 8 warps: 4(m) x 2(n))
// ---------------------------------------------------------------------------
__global__ __launch_bounds__(256, 2)
void lstm_gemm_kernel(const float* __restrict__ c_in, float* __restrict__ out) {
    extern __shared__ char smem[];
    const uint32_t smem_u32 = smem_to_u32(smem);
    const int tid = threadIdx.x;
    const int wid = tid >> 5;
    const int lane = tid & 31;
    const int warp_m = wid & 3;       // 0..3 -> 32 rows each
    const int warp_n = wid >> 2;      // 0..1 -> 64 cols each
    const int m0 = blockIdx.y * BM;
    const int r0 = blockIdx.x * BN;   // gate-interleaved column base
    const int jb = blockIdx.x * 32;   // hidden-unit base

    float* bias_s = reinterpret_cast<float*>(smem + SMEM_BIAS);
    if (tid < 128) bias_s[tid] = g_bias[r0 + tid];

    // --- cp.async producers: incrementally advanced pointers --------------
    const int ci = tid & 7;           // 16B chunk in a 128B row
    const int crb = tid >> 3;         // row base (0..31)
    const __half* pA[4];
    const __half* pB[4];
    uint32_t swoff[4];
    #pragma unroll
    for (int rep = 0; rep < 4; ++rep) {
        const int row = crb + rep * 32;
        swoff[rep] = (uint32_t)(row * 128 + ((ci ^ (row & 7)) << 4));
        pA[rep] = g_A  + (size_t)(m0 + row) * KDIM + ci * 8;
        pB[rep] = g_Wt + (size_t)(r0 + row) * KDIM + ci * 8;
    }

    // load from current pA/pB into stage base `sm`, then advance by BK.
    auto load_stage_adv = [&](uint32_t sm) {
        #pragma unroll
        for (int rep = 0; rep < 4; ++rep) {
            cp_async_16(sm + swoff[rep], pA[rep]);
            cp_async_16(sm + BM * 128 + swoff[rep], pB[rep]);
            pA[rep] += BK;
            pB[rep] += BK;
        }
    };

    // prologue: stages 0,1 (groups #0, #1)
    load_stage_adv(smem_u32);
    CP_COMMIT();
    load_stage_adv(smem_u32 + STAGE_BYTES);
    CP_COMMIT();

    float acc[2][8][4];
    #pragma unroll
    for (int mt = 0; mt < 2; ++mt)
        #pragma unroll
        for (int nt = 0; nt < 8; ++nt)
            #pragma unroll
            for (int e = 0; e < 4; ++e) acc[mt][nt][e] = 0.0f;

    const int lrow = lane & 15;
    const int lhalf = lane >> 4;

    // Hoisted ldmatrix row offsets. Stage bases are 32KB-aligned and row*128
    // has bits[4:6] clear, so the swizzle XOR applies to the full address.
    uint32_t rowA[2], rowB[4];
    #pragma unroll
    for (int mt = 0; mt < 2; ++mt) {
        const int row = warp_m * 32 + mt * 16 + lrow;
        rowA[mt] = (uint32_t)(row * 128 + ((row & 7) << 4));
    }
    #pragma unroll
    for (int nt2 = 0; nt2 < 4; ++nt2) {
        const int row = warp_n * 64 + nt2 * 16 + lrow;
        rowB[nt2] = (uint32_t)(row * 128 + ((row & 7) << 4));
    }

    // Rotating stage bases (no %3): sc = compute stage, sp = prefetch stage.
    uint32_t scBase = smem_u32;                      // stage 0
    uint32_t spBase = smem_u32 + 2 * STAGE_BYTES;    // stage 2
    const uint32_t smTop = smem_u32 + 2 * STAGE_BYTES;

    // Per chunk: sync (protect overwrite) -> issue prefetch -> commit ->
    // wait for compute stage -> ldmatrix+mma. Prefetch issue overlaps wait.
    #pragma unroll 1
    for (int c = 0; c < NCHUNK; ++c) {
        __syncthreads();               // everyone done reading slot spBase
        if (c + 2 < NCHUNK)
            load_stage_adv(spBase);
        CP_COMMIT();                   // group #(c+2); empty near tail is fine
        CP_WAIT(2);                    // group #c done -> stage sc resident
        __syncthreads();               // all threads' stage-sc parts visible

        const uint32_t smA = scBase;
        const uint32_t smB = scBase + BM * 128;

        #pragma unroll
        for (int ks = 0; ks < 4; ++ks) {
            const uint32_t cx = (uint32_t)((ks * 2 + lhalf) << 4);
            uint32_t a[2][4];
            #pragma unroll
            for (int mt = 0; mt < 2; ++mt)
                ldmatrix_x4(a[mt][0], a[mt][1], a[mt][2], a[mt][3],
                            (smA + rowA[mt]) ^ cx);
            uint32_t b[4][4];
            #pragma unroll
            for (int nt2 = 0; nt2 < 4; ++nt2)
                ldmatrix_x4(b[nt2][0], b[nt2][1], b[nt2][2], b[nt2][3],
                            (smB + rowB[nt2]) ^ cx);
            #pragma unroll
            for (int mt = 0; mt < 2; ++mt)
                #pragma unroll
                for (int nt = 0; nt < 8; ++nt)
                    mma_fp16(acc[mt][nt], a[mt],
                             b[nt >> 1][nt & 1], b[nt >> 1][(nt & 1) + 2]);
        }

        scBase = (scBase == smTop) ? smem_u32 : scBase + STAGE_BYTES;
        spBase = (spBase == smTop) ? smem_u32 : spBase + STAGE_BYTES;
    }

    // ---------------- epilogue: stage z through smem, fuse LSTM ----------------
    CP_WAIT(0);
    __syncthreads();
    float* zbuf = reinterpret_cast<float*>(smem);
    {
        const int rb = warp_m * 32 + (lane >> 2);
        const int cb = warp_n * 64 + (lane & 3) * 2;
        #pragma unroll
        for (int mt = 0; mt < 2; ++mt)
            #pragma unroll
            for (int nt = 0; nt < 8; ++nt) {
                const int r = rb + mt * 16;
                const int cc = cb + nt * 8;
                zbuf[r * ZSTRIDE + cc]           = acc[mt][nt][0];
                zbuf[r * ZSTRIDE + cc + 1]       = acc[mt][nt][1];
                zbuf[(r + 8) * ZSTRIDE + cc]     = acc[mt][nt][2];
                zbuf[(r + 8) * ZSTRIDE + cc + 1] = acc[mt][nt][3];
            }
    }
    __syncthreads();

    {
        const int r = tid >> 1;                 // 0..127 local row
        const int jh = (tid & 1) * 16;          // 16 hidden units per thread
        const size_t m = (size_t)(m0 + r);
        const float* cin = c_in + m * HDIM + jb;
        float* hout = out + m * HDIM + jb;
        float* cout = out + (size_t)MDIM * HDIM + m * HDIM + jb;
        const float* zrow = zbuf + r * ZSTRIDE;

        #pragma unroll
        for (int q = 0; q < 4; ++q) {
            const int j0 = jh + q * 4;
            float4 ci4 = *reinterpret_cast<const float4*>(cin + j0);
            const float* cip = &ci4.x;
            float hv[4], cv[4];
            #pragma unroll
            for (int e = 0; e < 4; ++e) {
                const int j = j0 + e;
                float4 z4 = *reinterpret_cast<const float4*>(zrow + j * 4);
                float4 b4 = *reinterpret_cast<const float4*>(bias_s + j * 4);
                float zf = z4.x + b4.x, zi = z4.y + b4.y;
                float zg = z4.z + b4.z, zo = z4.w + b4.w;
                float f = 1.0f / (1.0f + __expf(-zf));
                float i = 1.0f / (1.0f + __expf(-zi));
                float g = tanhf(zg);
                float o = 1.0f / (1.0f + __expf(-zo));
                float cval = f * cip[e] + g * i;
                cv[e] = cval;
                hv[e] = tanhf(cval) * o;
            }
            *reinterpret_cast<float4*>(hout + j0) =
                make_float4(hv[0], hv[1], hv[2], hv[3]);
            *reinterpret_cast<float4*>(cout + j0) =
                make_float4(cv[0], cv[1], cv[2], cv[3]);
        }
    }
}

// ---------------------------------------------------------------------------
// kernel_launch
// ---------------------------------------------------------------------------
extern "C" void kernel_launch(void* const* d_in, const int* in_sizes, int n_in,
                              void* d_out, int out_size) {
    const float* x    = (const float*)d_in[0];
    const float* h_in = (const float*)d_in[1];
    const float* c_in = (const float*)d_in[2];
    const float* Wf   = (const float*)d_in[3];
    const float* bf   = (const float*)d_in[4];
    const float* Wi   = (const float*)d_in[5];
    const float* bi   = (const float*)d_in[6];
    const float* Wg   = (const float*)d_in[7];
    const float* bg   = (const float*)d_in[8];
    const float* Wo   = (const float*)d_in[9];
    const float* bo   = (const float*)d_in[10];
    float* out = (float*)d_out;

    pack_a_kernel<<<(MDIM * KDIM / 4) / 256, 256>>>(x, h_in);
    transpose_w_kernel<<<dim3(HDIM / 32, KDIM / 32, 4), dim3(32, 8)>>>(Wf, Wi, Wg, Wo);
    pack_bias_kernel<<<4, 256>>>(bf, bi, bg, bo);

    cudaFuncSetAttribute(lstm_gemm_kernel,
                         cudaFuncAttributeMaxDynamicSharedMemorySize, SMEM_TOTAL);
    lstm_gemm_kernel<<<dim3(NDIM / BN, MDIM / BM), 256, SMEM_TOTAL>>>(c_in, out);
}